// round 1
// baseline (speedup 1.0000x reference)
#include <cuda_runtime.h>
#include <math.h>

#define Bb 4
#define Ss 4096
#define Hh 8
#define Dd 64
#define HD (Hh*Dd)          // 512
#define NC 64
#define CS (Ss/NC)          // 64
#define BSn (Bb*Ss)         // 16384
#define Mm (Bb*Ss*Hh)       // 131072

// ---- scratch (device globals: allocation-free under harness rules) ----
__device__ float g_csum[Bb*Ss*Hh*Dd];
__device__ float g_fg  [Bb*Ss*Hh*Dd];
__device__ float g_igh [Bb*Ss*Hh*Dd];
__device__ float g_cell[Bb*Ss*Hh*Dd];
__device__ float g_mean[BSn];
__device__ float g_rinv[BSn];
__device__ float g_ctot[Bb*NC*HD];
__device__ float g_a   [Bb*NC*HD];
__device__ float g_bv  [Bb*NC*HD];
__device__ float g_cellin[Bb*NC*HD];

__device__ __forceinline__ float sigmf(float z){ return 1.f/(1.f+__expf(-z)); }

// ---- K1: per-chunk totals of x along S (for decoupled cumsum) ----
__global__ void k_chunksum(const float* __restrict__ x){
    int bc = blockIdx.x; int b = bc>>6; int c = bc&63; int t = threadIdx.x;
    const float* p = x + (b*Ss + c*CS)*HD + t;
    float acc = 0.f;
    #pragma unroll 8
    for (int s=0;s<CS;s++) acc += p[s*HD];
    g_ctot[bc*HD + t] = acc;
}

// ---- K2: exclusive scan of chunk totals (per (b, h*d) channel) ----
__global__ void k_chunkscan(){
    int ch = blockIdx.x*blockDim.x + threadIdx.x;   // 0..2047
    int b = ch>>9, t = ch&511;
    float run = 0.f;
    #pragma unroll
    for (int c=0;c<NC;c++){
        int i = (b*NC + c)*HD + t;
        float v = g_ctot[i]; g_ctot[i] = run; run += v;
    }
}

// ---- K3: materialize exclusive cumsum + per-(b,s) LN stats ----
__global__ void k_csum_stats(const float* __restrict__ x){
    int bc = blockIdx.x; int b = bc>>6; int c = bc&63; int t = threadIdx.x;
    int lane = t&31, wid = t>>5;
    __shared__ float r1[16], r2[16];
    float run = g_ctot[bc*HD + t];
    int base = (b*Ss + c*CS)*HD + t;
    for (int s=0;s<CS;s++){
        float v = run;
        g_csum[base + s*HD] = v;
        run += x[base + s*HD];
        float s1 = v, s2 = v*v;
        #pragma unroll
        for (int o=16;o;o>>=1){
            s1 += __shfl_xor_sync(0xffffffffu, s1, o);
            s2 += __shfl_xor_sync(0xffffffffu, s2, o);
        }
        if (lane==0){ r1[wid]=s1; r2[wid]=s2; }
        __syncthreads();
        if (t<16){
            s1 = r1[t]; s2 = r2[t];
            #pragma unroll
            for (int o=8;o;o>>=1){
                s1 += __shfl_xor_sync(0x0000ffffu, s1, o);
                s2 += __shfl_xor_sync(0x0000ffffu, s2, o);
            }
            if (t==0){
                float mean = s1*(1.f/HD);
                float var  = s2*(1.f/HD) - mean*mean;
                int si = b*Ss + c*CS + s;
                g_mean[si] = mean;
                g_rinv[si] = rsqrtf(var + 1e-5f);
            }
        }
        __syncthreads();
    }
}

// ---- K4: GEMM1 (A=[x | LN(csum)], W_hid 128x192) + gates -> fg, igh ----
__global__ __launch_bounds__(256) void k_gemm1(
    const float* __restrict__ x, const float* __restrict__ W,
    const float* __restrict__ bias, const float* __restrict__ gamma,
    const float* __restrict__ beta){
    __shared__ float As[64][33];
    __shared__ float Bs[32][192];
    __shared__ float gsm[512], bsm[512], bb[192];
    int t = threadIdx.x;
    for (int i=t;i<512;i+=256){ gsm[i]=gamma[i]; bsm[i]=beta[i]; }
    if (t<192) bb[t] = bias[t];
    __syncthreads();

    int r0 = blockIdx.x*64;
    int ct = t&31, rt = t>>5;
    float acc[8][6];
    #pragma unroll
    for (int i=0;i<8;i++)
        #pragma unroll
        for (int j=0;j<6;j++) acc[i][j]=0.f;

    for (int k0=0;k0<128;k0+=32){
        #pragma unroll
        for (int i=0;i<8;i++){
            int idx = t + i*256;
            int row = idx>>5, kk = idx&31;
            int r = r0 + row;
            float v;
            if (k0 < 64){
                v = x[r*64 + k0 + kk];
            } else {
                int kc = k0 - 64 + kk;
                float cc = g_csum[r*64 + kc];
                int bs = r>>3;
                v = (cc - g_mean[bs])*g_rinv[bs]*gsm[(r&7)*64 + kc] + bsm[(r&7)*64 + kc];
            }
            As[row][kk] = v;
        }
        #pragma unroll
        for (int i=0;i<24;i++){
            int idx = t + i*256;
            int row = idx/192, col = idx - row*192;
            Bs[row][col] = W[(k0+row)*192 + col];
        }
        __syncthreads();
        #pragma unroll 4
        for (int k=0;k<32;k++){
            float a[8], bf[6];
            #pragma unroll
            for (int j=0;j<6;j++) bf[j] = Bs[k][ct + 32*j];
            #pragma unroll
            for (int i=0;i<8;i++) a[i] = As[rt*8+i][k];
            #pragma unroll
            for (int i=0;i<8;i++)
                #pragma unroll
                for (int j=0;j<6;j++) acc[i][j] += a[i]*bf[j];
        }
        __syncthreads();
    }
    #pragma unroll
    for (int i=0;i<8;i++){
        int r = r0 + rt*8 + i;
        #pragma unroll
        for (int jj=0;jj<2;jj++){
            int col = ct + 32*jj;
            float ig = acc[i][jj]   + bb[col];
            float fg = acc[i][jj+2] + bb[col+64];
            float hd = acc[i][jj+4] + bb[col+128];
            g_fg [r*64 + col] = sigmf(fg);
            g_igh[r*64 + col] = sigmf(ig) * fmaxf(hd, 0.f);
        }
    }
}

// ---- K5: per-chunk affine scan coefficients (a, b) ----
__global__ void k_seg_ab(){
    int bc = blockIdx.x; int t = threadIdx.x;
    int b = bc>>6, c = bc&63;
    int base = (b*Ss + c*CS)*HD + t;
    float a = 1.f, bb2 = 0.f;
    #pragma unroll 8
    for (int s=0;s<CS;s++){
        float f = g_fg[base + s*HD];
        float g = g_igh[base + s*HD];
        a *= f; bb2 = bb2*f + g;
    }
    g_a[bc*HD + t] = a; g_bv[bc*HD + t] = bb2;
}

// ---- K6: chunk-carry scan: cell value entering each chunk ----
__global__ void k_carry(const float* __restrict__ initcx){
    int ch = blockIdx.x*blockDim.x + threadIdx.x;
    int b = ch>>9, t = ch&511;
    float cell = initcx[t];
    #pragma unroll
    for (int c=0;c<NC;c++){
        int i = (b*NC + c)*HD + t;
        g_cellin[i] = cell;
        cell = g_a[i]*cell + g_bv[i];
    }
}

// ---- K7: in-chunk cell recurrence ----
__global__ void k_cell(){
    int bc = blockIdx.x; int t = threadIdx.x;
    int b = bc>>6, c = bc&63;
    int base = (b*Ss + c*CS)*HD + t;
    float cell = g_cellin[bc*HD + t];
    #pragma unroll 8
    for (int s=0;s<CS;s++){
        cell = g_fg[base + s*HD]*cell + g_igh[base + s*HD];
        g_cell[base + s*HD] = cell;
    }
}

// ---- K8: GEMM2 (A=[x | cell], W_og 128x64) + sigmoid*cell -> out ----
__global__ __launch_bounds__(256) void k_gemm2(
    const float* __restrict__ x, const float* __restrict__ W,
    const float* __restrict__ bias, float* __restrict__ out){
    __shared__ float As[128][33];
    __shared__ float Bs[32][64];
    __shared__ float bb[64];
    int t = threadIdx.x;
    if (t<64) bb[t] = bias[t];

    int r0 = blockIdx.x*128;
    int ct = t&15, rt = t>>4;
    float acc[8][4];
    #pragma unroll
    for (int i=0;i<8;i++)
        #pragma unroll
        for (int j=0;j<4;j++) acc[i][j]=0.f;

    for (int k0=0;k0<128;k0+=32){
        const float* src = (k0<64) ? x : g_cell;
        int koff = (k0<64) ? k0 : (k0-64);
        #pragma unroll
        for (int i=0;i<16;i++){
            int idx = t + i*256;
            int row = idx>>5, kk = idx&31;
            As[row][kk] = src[(r0+row)*64 + koff + kk];
        }
        #pragma unroll
        for (int i=0;i<8;i++){
            int idx = t + i*256;
            int row = idx>>6, col = idx&63;
            Bs[row][col] = W[(k0+row)*64 + col];
        }
        __syncthreads();
        #pragma unroll 4
        for (int k=0;k<32;k++){
            float a[8], bf[4];
            #pragma unroll
            for (int j=0;j<4;j++) bf[j] = Bs[k][ct + 16*j];
            #pragma unroll
            for (int i=0;i<8;i++) a[i] = As[rt*8+i][k];
            #pragma unroll
            for (int i=0;i<8;i++)
                #pragma unroll
                for (int j=0;j<4;j++) acc[i][j] += a[i]*bf[j];
        }
        __syncthreads();
    }
    #pragma unroll
    for (int i=0;i<8;i++){
        int r = r0 + rt*8 + i;
        #pragma unroll
        for (int j=0;j<4;j++){
            int col = ct + 16*j;
            float og = sigmf(acc[i][j] + bb[col]);
            float cv = g_cell[r*64 + col];
            out[r*64 + col] = og*cv;
        }
    }
}

extern "C" void kernel_launch(void* const* d_in, const int* in_sizes, int n_in,
                              void* d_out, int out_size){
    const float* x      = (const float*)d_in[0];
    const float* W_hid  = (const float*)d_in[1];
    const float* b_hid  = (const float*)d_in[2];
    const float* W_og   = (const float*)d_in[3];
    const float* b_og   = (const float*)d_in[4];
    const float* gamma  = (const float*)d_in[5];
    const float* beta   = (const float*)d_in[6];
    const float* initcx = (const float*)d_in[7];
    float* out = (float*)d_out;

    k_chunksum  <<<Bb*NC, 512>>>(x);
    k_chunkscan <<<16, 128>>>();
    k_csum_stats<<<Bb*NC, 512>>>(x);
    k_gemm1     <<<Mm/64, 256>>>(x, W_hid, b_hid, gamma, beta);
    k_seg_ab    <<<Bb*NC, 512>>>();
    k_carry     <<<16, 128>>>(initcx);
    k_cell      <<<Bb*NC, 512>>>();
    k_gemm2     <<<Mm/128, 256>>>(x, W_og, b_og, out);
}

// round 3
// speedup vs baseline: 1.1770x; 1.1770x over previous
#include <cuda_runtime.h>
#include <math.h>

#define Bb 4
#define Ss 4096
#define Hh 8
#define Dd 64
#define HD (Hh*Dd)          // 512
#define NC 64
#define CS (Ss/NC)          // 64
#define BSn (Bb*Ss)         // 16384
#define Mm (Bb*Ss*Hh)       // 131072

// ---- scratch ----
__device__ float g_csum[Bb*Ss*Hh*Dd];
__device__ float g_fg  [Bb*Ss*Hh*Dd];
__device__ float g_igh [Bb*Ss*Hh*Dd];
__device__ float g_cell[Bb*Ss*Hh*Dd];
__device__ float g_mean[BSn];
__device__ float g_rinv[BSn];
__device__ float g_ctot[Bb*NC*HD];
__device__ float g_a   [Bb*NC*HD];
__device__ float g_bv  [Bb*NC*HD];
__device__ float g_cellin[Bb*NC*HD];

__device__ __forceinline__ float sigmf(float z){ return 1.f/(1.f+__expf(-z)); }

__device__ __forceinline__ void split_tf32(float v, float &hf, float &lf){
    unsigned h;
    asm("cvt.rna.tf32.f32 %0, %1;" : "=r"(h) : "f"(v));
    hf = __uint_as_float(h);
    lf = v - hf;
}

__device__ __forceinline__ void mma8(float* c, const unsigned* a, unsigned b0, unsigned b1){
    asm volatile("mma.sync.aligned.m16n8k8.row.col.f32.tf32.tf32.f32 "
        "{%0,%1,%2,%3}, {%4,%5,%6,%7}, {%8,%9}, {%0,%1,%2,%3};"
        : "+f"(c[0]),"+f"(c[1]),"+f"(c[2]),"+f"(c[3])
        : "r"(a[0]),"r"(a[1]),"r"(a[2]),"r"(a[3]), "r"(b0),"r"(b1));
}

// ---- K1: per-chunk totals ----
__global__ void k_chunksum(const float* __restrict__ x){
    int bc = blockIdx.x; int b = bc>>6; int c = bc&63; int t = threadIdx.x;
    const float* p = x + (b*Ss + c*CS)*HD + t;
    float acc = 0.f;
    #pragma unroll 8
    for (int s=0;s<CS;s++) acc += p[s*HD];
    g_ctot[bc*HD + t] = acc;
}

// ---- K2: exclusive scan of chunk totals ----
__global__ void k_chunkscan(){
    int ch = blockIdx.x*blockDim.x + threadIdx.x;
    int b = ch>>9, t = ch&511;
    float run = 0.f;
    #pragma unroll
    for (int c=0;c<NC;c++){
        int i = (b*NC + c)*HD + t;
        float v = g_ctot[i]; g_ctot[i] = run; run += v;
    }
}

// ---- K3: materialize exclusive cumsum + LN stats ----
__global__ void k_csum_stats(const float* __restrict__ x){
    int bc = blockIdx.x; int b = bc>>6; int c = bc&63; int t = threadIdx.x;
    int lane = t&31, wid = t>>5;
    __shared__ float r1[16], r2[16];
    float run = g_ctot[bc*HD + t];
    int base = (b*Ss + c*CS)*HD + t;
    for (int s=0;s<CS;s++){
        float v = run;
        g_csum[base + s*HD] = v;
        run += x[base + s*HD];
        float s1 = v, s2 = v*v;
        #pragma unroll
        for (int o=16;o;o>>=1){
            s1 += __shfl_xor_sync(0xffffffffu, s1, o);
            s2 += __shfl_xor_sync(0xffffffffu, s2, o);
        }
        if (lane==0){ r1[wid]=s1; r2[wid]=s2; }
        __syncthreads();
        if (t<16){
            s1 = r1[t]; s2 = r2[t];
            #pragma unroll
            for (int o=8;o;o>>=1){
                s1 += __shfl_xor_sync(0x0000ffffu, s1, o);
                s2 += __shfl_xor_sync(0x0000ffffu, s2, o);
            }
            if (t==0){
                float mean = s1*(1.f/HD);
                float var  = s2*(1.f/HD) - mean*mean;
                int si = b*Ss + c*CS + s;
                g_mean[si] = mean;
                g_rinv[si] = rsqrtf(var + 1e-5f);
            }
        }
        __syncthreads();
    }
}

// ---- K4: GEMM1 via 3xTF32 mma.sync, fused LN A-tile + gate epilogue ----
// Block tile M=128, d-range 32 (-> 96 actual W columns {ig,fg,hd}).
// Warps: 4 in M (32 rows each) x 2 in d (16 each -> 48 smem cols).
__global__ __launch_bounds__(256) void k_gemm1(
    const float* __restrict__ x, const float* __restrict__ W,
    const float* __restrict__ bias, const float* __restrict__ gamma,
    const float* __restrict__ beta){
    __shared__ float Ah[128*20], Al[128*20];
    __shared__ float Bh[16*104], Bl[16*104];
    __shared__ float gsm[512], bsm[512], bbs[96];
    int t = threadIdx.x;
    int r0 = blockIdx.x*128;
    int n0d = blockIdx.y*32;
    for (int i=t;i<512;i+=256){ gsm[i]=gamma[i]; bsm[i]=beta[i]; }
    if (t<96){
        int wnn=t/48, rem=t%48, gate=rem>>4, dd=rem&15;
        bbs[t] = bias[gate*64 + n0d + wnn*16 + dd];
    }

    int lane=t&31, wid=t>>5, wm=wid&3, wn=wid>>2;
    int g=lane>>2, tg=lane&3;
    float Cr[2][6][4];
    #pragma unroll
    for (int a=0;a<2;a++)
        #pragma unroll
        for (int b=0;b<6;b++)
            #pragma unroll
            for (int c=0;c<4;c++) Cr[a][b][c]=0.f;

    for (int k0=0;k0<128;k0+=16){
        // A stage (128x16)
        #pragma unroll
        for (int i=0;i<8;i++){
            int idx=t+i*256; int row=idx>>4, kk=idx&15;
            int r=r0+row; float v;
            if (k0<64){
                v = x[r*64 + k0 + kk];
            } else {
                int kc = k0-64+kk;
                float cc = g_csum[r*64 + kc];
                int bs = r>>3;
                v = (cc - g_mean[bs])*g_rinv[bs]*gsm[(r&7)*64+kc] + bsm[(r&7)*64+kc];
            }
            float hf,lf; split_tf32(v,hf,lf);
            Ah[row*20+kk]=hf; Al[row*20+kk]=lf;
        }
        // B stage (16x96, remapped gate-interleaved columns)
        #pragma unroll
        for (int i=0;i<6;i++){
            int idx=t+i*256; int row=idx/96, c=idx-row*96;
            int wnn=c/48, rem=c-wnn*48, gate=rem>>4, dd=rem&15;
            float v = W[(k0+row)*192 + gate*64 + n0d + wnn*16 + dd];
            float hf,lf; split_tf32(v,hf,lf);
            Bh[row*104+c]=hf; Bl[row*104+c]=lf;
        }
        __syncthreads();
        #pragma unroll
        for (int ks=0;ks<16;ks+=8){
            unsigned ah[2][4], al[2][4];
            #pragma unroll
            for (int mf=0;mf<2;mf++){
                int mr = wm*32+mf*16;
                ah[mf][0]=__float_as_uint(Ah[(mr+g  )*20+ks+tg  ]);
                ah[mf][1]=__float_as_uint(Ah[(mr+g+8)*20+ks+tg  ]);
                ah[mf][2]=__float_as_uint(Ah[(mr+g  )*20+ks+tg+4]);
                ah[mf][3]=__float_as_uint(Ah[(mr+g+8)*20+ks+tg+4]);
                al[mf][0]=__float_as_uint(Al[(mr+g  )*20+ks+tg  ]);
                al[mf][1]=__float_as_uint(Al[(mr+g+8)*20+ks+tg  ]);
                al[mf][2]=__float_as_uint(Al[(mr+g  )*20+ks+tg+4]);
                al[mf][3]=__float_as_uint(Al[(mr+g+8)*20+ks+tg+4]);
            }
            #pragma unroll
            for (int nf=0;nf<6;nf++){
                int cb = wn*48 + nf*8 + g;
                unsigned bh0=__float_as_uint(Bh[(ks+tg  )*104+cb]);
                unsigned bh1=__float_as_uint(Bh[(ks+tg+4)*104+cb]);
                unsigned bl0=__float_as_uint(Bl[(ks+tg  )*104+cb]);
                unsigned bl1=__float_as_uint(Bl[(ks+tg+4)*104+cb]);
                #pragma unroll
                for (int mf=0;mf<2;mf++){
                    mma8(Cr[mf][nf], ah[mf], bh0, bh1);
                    mma8(Cr[mf][nf], ah[mf], bl0, bl1);
                    mma8(Cr[mf][nf], al[mf], bh0, bh1);
                }
            }
        }
        __syncthreads();
    }
    // epilogue: gates
    #pragma unroll
    for (int mf=0;mf<2;mf++)
        #pragma unroll
        for (int nfd=0;nfd<2;nfd++)
            #pragma unroll
            for (int j=0;j<4;j++){
                int row = r0 + wm*32 + mf*16 + g + ((j>>1)<<3);
                int colf = 2*tg + (j&1);
                int d = n0d + wn*16 + nfd*8 + colf;
                int cb = wn*48 + nfd*8 + colf;
                float ig  = Cr[mf][nfd  ][j] + bbs[cb];
                float fgv = Cr[mf][nfd+2][j] + bbs[cb+16];
                float hd  = Cr[mf][nfd+4][j] + bbs[cb+32];
                g_fg [row*64+d] = sigmf(fgv);
                g_igh[row*64+d] = sigmf(ig)*fmaxf(hd,0.f);
            }
}

// ---- K5: per-chunk affine scan coefficients ----
__global__ void k_seg_ab(){
    int bc = blockIdx.x; int t = threadIdx.x;
    int b = bc>>6, c = bc&63;
    int base = (b*Ss + c*CS)*HD + t;
    float a = 1.f, bb2 = 0.f;
    #pragma unroll 8
    for (int s=0;s<CS;s++){
        float f = g_fg[base + s*HD];
        float g = g_igh[base + s*HD];
        a *= f; bb2 = bb2*f + g;
    }
    g_a[bc*HD + t] = a; g_bv[bc*HD + t] = bb2;
}

// ---- K6: chunk-carry scan ----
__global__ void k_carry(const float* __restrict__ initcx){
    int ch = blockIdx.x*blockDim.x + threadIdx.x;
    int b = ch>>9, t = ch&511;
    float cell = initcx[t];
    #pragma unroll
    for (int c=0;c<NC;c++){
        int i = (b*NC + c)*HD + t;
        g_cellin[i] = cell;
        cell = g_a[i]*cell + g_bv[i];
    }
}

// ---- K7: in-chunk cell recurrence ----
__global__ void k_cell(){
    int bc = blockIdx.x; int t = threadIdx.x;
    int b = bc>>6, c = bc&63;
    int base = (b*Ss + c*CS)*HD + t;
    float cell = g_cellin[bc*HD + t];
    #pragma unroll 8
    for (int s=0;s<CS;s++){
        cell = g_fg[base + s*HD]*cell + g_igh[base + s*HD];
        g_cell[base + s*HD] = cell;
    }
}

// ---- K8: GEMM2 via 3xTF32 mma.sync, fused sigmoid*cell epilogue ----
__global__ __launch_bounds__(256) void k_gemm2(
    const float* __restrict__ x, const float* __restrict__ W,
    const float* __restrict__ bias, float* __restrict__ out){
    __shared__ float Ah[128*20], Al[128*20];
    __shared__ float Bh[16*72], Bl[16*72];
    __shared__ float bbs[64];
    int t = threadIdx.x;
    int r0 = blockIdx.x*128;
    if (t<64) bbs[t] = bias[t];

    int lane=t&31, wid=t>>5, wm=wid&3, wn=wid>>2;
    int g=lane>>2, tg=lane&3;
    float Cr[2][4][4];
    #pragma unroll
    for (int a=0;a<2;a++)
        #pragma unroll
        for (int b=0;b<4;b++)
            #pragma unroll
            for (int c=0;c<4;c++) Cr[a][b][c]=0.f;

    for (int k0=0;k0<128;k0+=16){
        const float* src = (k0<64) ? x : g_cell;
        int koff = (k0<64) ? k0 : (k0-64);
        #pragma unroll
        for (int i=0;i<8;i++){
            int idx=t+i*256; int row=idx>>4, kk=idx&15;
            float v = src[(r0+row)*64 + koff + kk];
            float hf,lf; split_tf32(v,hf,lf);
            Ah[row*20+kk]=hf; Al[row*20+kk]=lf;
        }
        #pragma unroll
        for (int i=0;i<4;i++){
            int idx=t+i*256; int row=idx>>6, c=idx&63;
            float v = W[(k0+row)*64 + c];
            float hf,lf; split_tf32(v,hf,lf);
            Bh[row*72+c]=hf; Bl[row*72+c]=lf;
        }
        __syncthreads();
        #pragma unroll
        for (int ks=0;ks<16;ks+=8){
            unsigned ah[2][4], al[2][4];
            #pragma unroll
            for (int mf=0;mf<2;mf++){
                int mr = wm*32+mf*16;
                ah[mf][0]=__float_as_uint(Ah[(mr+g  )*20+ks+tg  ]);
                ah[mf][1]=__float_as_uint(Ah[(mr+g+8)*20+ks+tg  ]);
                ah[mf][2]=__float_as_uint(Ah[(mr+g  )*20+ks+tg+4]);
                ah[mf][3]=__float_as_uint(Ah[(mr+g+8)*20+ks+tg+4]);
                al[mf][0]=__float_as_uint(Al[(mr+g  )*20+ks+tg  ]);
                al[mf][1]=__float_as_uint(Al[(mr+g+8)*20+ks+tg  ]);
                al[mf][2]=__float_as_uint(Al[(mr+g  )*20+ks+tg+4]);
                al[mf][3]=__float_as_uint(Al[(mr+g+8)*20+ks+tg+4]);
            }
            #pragma unroll
            for (int nf=0;nf<4;nf++){
                int cb = wn*32 + nf*8 + g;
                unsigned bh0=__float_as_uint(Bh[(ks+tg  )*72+cb]);
                unsigned bh1=__float_as_uint(Bh[(ks+tg+4)*72+cb]);
                unsigned bl0=__float_as_uint(Bl[(ks+tg  )*72+cb]);
                unsigned bl1=__float_as_uint(Bl[(ks+tg+4)*72+cb]);
                #pragma unroll
                for (int mf=0;mf<2;mf++){
                    mma8(Cr[mf][nf], ah[mf], bh0, bh1);
                    mma8(Cr[mf][nf], ah[mf], bl0, bl1);
                    mma8(Cr[mf][nf], al[mf], bh0, bh1);
                }
            }
        }
        __syncthreads();
    }
    #pragma unroll
    for (int mf=0;mf<2;mf++)
        #pragma unroll
        for (int nf=0;nf<4;nf++)
            #pragma unroll
            for (int j=0;j<4;j++){
                int row = r0 + wm*32 + mf*16 + g + ((j>>1)<<3);
                int col = wn*32 + nf*8 + 2*tg + (j&1);
                float og = sigmf(Cr[mf][nf][j] + bbs[col]);
                out[row*64+col] = og * g_cell[row*64+col];
            }
}

extern "C" void kernel_launch(void* const* d_in, const int* in_sizes, int n_in,
                              void* d_out, int out_size){
    const float* x      = (const float*)d_in[0];
    const float* W_hid  = (const float*)d_in[1];
    const float* b_hid  = (const float*)d_in[2];
    const float* W_og   = (const float*)d_in[3];
    const float* b_og   = (const float*)d_in[4];
    const float* gamma  = (const float*)d_in[5];
    const float* beta   = (const float*)d_in[6];
    const float* initcx = (const float*)d_in[7];
    float* out = (float*)d_out;

    k_chunksum  <<<Bb*NC, 512>>>(x);
    k_chunkscan <<<16, 128>>>();
    k_csum_stats<<<Bb*NC, 512>>>(x);
    k_gemm1     <<<dim3(Mm/128, 2), 256>>>(x, W_hid, b_hid, gamma, beta);
    k_seg_ab    <<<Bb*NC, 512>>>();
    k_carry     <<<16, 128>>>(initcx);
    k_cell      <<<Bb*NC, 512>>>();
    k_gemm2     <<<Mm/128, 256>>>(x, W_og, b_og, out);
}

// round 4
// speedup vs baseline: 1.6043x; 1.3630x over previous
#include <cuda_runtime.h>
#include <cuda_bf16.h>
#include <math.h>

#define Bb 4
#define Ss 4096
#define Hh 8
#define Dd 64
#define HD 512
#define NC 64
#define CS 64
#define BSn 16384
#define Mm 131072          // B*S*H rows
#define MD (Mm*64)         // 8.39M elems

// ---- fp32 scratch ----
__device__ float g_csum[MD];
__device__ float g_fg  [MD];
__device__ float g_igh [MD];
__device__ float g_cell[MD];
__device__ float g_ctot[Bb*NC*HD];
__device__ float g_a   [Bb*NC*HD];
__device__ float g_bv  [Bb*NC*HD];
__device__ float g_cellin[Bb*NC*HD];
// ---- bf16 hi/lo operand scratch ----
__device__ __nv_bfloat16 g_xh[MD], g_xl[MD];
__device__ __nv_bfloat16 g_lnh[MD], g_lnl[MD];
__device__ __nv_bfloat16 g_ch[MD], g_cl[MD];
__device__ __nv_bfloat16 g_W1h[192*128], g_W1l[192*128];   // [c][k], gate-remapped
__device__ __nv_bfloat16 g_W2h[64*128],  g_W2l[64*128];    // [n][k]

__device__ __forceinline__ float sigmf(float z){ return 1.f/(1.f+__expf(-z)); }

__device__ __forceinline__ void split_bf16(float v, __nv_bfloat16 &h, __nv_bfloat16 &l){
    h = __float2bfloat16(v);
    l = __float2bfloat16(v - __bfloat162float(h));
}

__device__ __forceinline__ void mma16(float* c, const unsigned* a, unsigned b0, unsigned b1){
    asm volatile("mma.sync.aligned.m16n8k16.row.col.f32.bf16.bf16.f32 "
        "{%0,%1,%2,%3}, {%4,%5,%6,%7}, {%8,%9}, {%0,%1,%2,%3};"
        : "+f"(c[0]),"+f"(c[1]),"+f"(c[2]),"+f"(c[3])
        : "r"(a[0]),"r"(a[1]),"r"(a[2]),"r"(a[3]), "r"(b0),"r"(b1));
}

// ---- P0: weight transpose + remap + split ----
__global__ void k_prepw(const float* __restrict__ W1, const float* __restrict__ W2){
    int c = blockIdx.x, k = threadIdx.x;
    if (c < 192){
        int wn=c/48, rem=c%48, gate=rem>>4, dd=rem&15;
        float v = W1[k*192 + gate*64 + wn*16 + dd];
        __nv_bfloat16 h,l; split_bf16(v,h,l);
        g_W1h[c*128+k]=h; g_W1l[c*128+k]=l;
    } else {
        int c2 = c-192;
        float v = W2[k*64 + c2];
        __nv_bfloat16 h,l; split_bf16(v,h,l);
        g_W2h[c2*128+k]=h; g_W2l[c2*128+k]=l;
    }
}

// ---- K1: per-chunk totals + x split to bf16 ----
__global__ void k_chunksum(const float* __restrict__ x){
    int bc = blockIdx.x; int b = bc>>6; int c = bc&63; int t = threadIdx.x;
    int base = (b*Ss + c*CS)*HD + t;
    float acc = 0.f;
    #pragma unroll 8
    for (int s=0;s<CS;s++){
        float v = x[base + s*HD];
        acc += v;
        __nv_bfloat16 h,l; split_bf16(v,h,l);
        g_xh[base+s*HD]=h; g_xl[base+s*HD]=l;
    }
    g_ctot[bc*HD + t] = acc;
}

// ---- K2: exclusive scan of chunk totals ----
__global__ void k_chunkscan(){
    int ch = blockIdx.x*blockDim.x + threadIdx.x;
    int b = ch>>9, t = ch&511;
    float run = 0.f;
    #pragma unroll
    for (int c=0;c<NC;c++){
        int i = (b*NC + c)*HD + t;
        float v = g_ctot[i]; g_ctot[i] = run; run += v;
    }
}

// ---- K3: materialize exclusive cumsum ----
__global__ void k_csum(const float* __restrict__ x){
    int bc = blockIdx.x; int b = bc>>6; int c = bc&63; int t = threadIdx.x;
    float run = g_ctot[bc*HD + t];
    int base = (b*Ss + c*CS)*HD + t;
    #pragma unroll 8
    for (int s=0;s<CS;s++){
        g_csum[base + s*HD] = run;
        run += x[base + s*HD];
    }
}

// ---- K4: LN stats + normalize + split (one warp per (b,s) row) ----
__global__ __launch_bounds__(512) void k_ln(const float* __restrict__ gamma,
                                            const float* __restrict__ beta){
    __shared__ float gsm[512], bsm[512];
    int t = threadIdx.x;
    gsm[t]=gamma[t]; bsm[t]=beta[t];
    __syncthreads();
    int lane = t&31;
    int row = blockIdx.x*16 + (t>>5);
    const float4* src = (const float4*)(g_csum + row*512);
    float4 v[4]; float s1=0.f, s2=0.f;
    #pragma unroll
    for (int i=0;i<4;i++){
        v[i] = src[i*32+lane];
        s1 += v[i].x+v[i].y+v[i].z+v[i].w;
        s2 += v[i].x*v[i].x+v[i].y*v[i].y+v[i].z*v[i].z+v[i].w*v[i].w;
    }
    #pragma unroll
    for (int o=16;o;o>>=1){
        s1 += __shfl_xor_sync(0xffffffffu, s1, o);
        s2 += __shfl_xor_sync(0xffffffffu, s2, o);
    }
    float mean = s1*(1.f/512.f);
    float rinv = rsqrtf(s2*(1.f/512.f) - mean*mean + 1e-5f);
    #pragma unroll
    for (int i=0;i<4;i++){
        int e0 = (i*32+lane)*4;
        float w0 = (v[i].x-mean)*rinv*gsm[e0  ]+bsm[e0  ];
        float w1 = (v[i].y-mean)*rinv*gsm[e0+1]+bsm[e0+1];
        float w2 = (v[i].z-mean)*rinv*gsm[e0+2]+bsm[e0+2];
        float w3 = (v[i].w-mean)*rinv*gsm[e0+3]+bsm[e0+3];
        __nv_bfloat16 h0,l0,h1,l1,h2,l2,h3,l3;
        split_bf16(w0,h0,l0); split_bf16(w1,h1,l1);
        split_bf16(w2,h2,l2); split_bf16(w3,h3,l3);
        __nv_bfloat162 ph0 = __halves2bfloat162(h0,h1), ph1 = __halves2bfloat162(h2,h3);
        __nv_bfloat162 pl0 = __halves2bfloat162(l0,l1), pl1 = __halves2bfloat162(l2,l3);
        uint2 uh; uh.x = *(unsigned*)&ph0; uh.y = *(unsigned*)&ph1;
        uint2 ul; ul.x = *(unsigned*)&pl0; ul.y = *(unsigned*)&pl1;
        ((uint2*)(g_lnh + row*512))[i*32+lane] = uh;
        ((uint2*)(g_lnl + row*512))[i*32+lane] = ul;
    }
}

// ---- K5: GEMM1 bf16-compensated mma, M64 x N192, fused gate epilogue ----
__global__ __launch_bounds__(256,2) void k_gemm1(const float* __restrict__ bias){
    __shared__ __nv_bfloat16 Ah[2][64*24], Al[2][64*24];
    __shared__ __nv_bfloat16 Bh[2][192*24], Bl[2][192*24];
    int t = threadIdx.x;
    int r0 = blockIdx.x*64;
    int lane=t&31, wid=t>>5, wm=wid&1, wn=wid>>1;
    int g=lane>>2, tg=lane&3;

    float Cr[2][6][4];
    #pragma unroll
    for (int a=0;a<2;a++)
        #pragma unroll
        for (int b=0;b<6;b++)
            #pragma unroll
            for (int c=0;c<4;c++) Cr[a][b][c]=0.f;

    unsigned ra_h[2], ra_l[2], rb_h[6], rb_l[6];

    // stage loader: s in 0..7 (k0 = s*16); s<4 -> x, else -> ln
    auto load_stage = [&](int s){
        const unsigned* gah = (const unsigned*)(s<4 ? g_xh : g_lnh);
        const unsigned* gal = (const unsigned*)(s<4 ? g_xl : g_lnl);
        int so = (s&3)*8;
        #pragma unroll
        for (int i=0;i<2;i++){
            int idx = t + i*256, row = idx>>3, c8 = idx&7;
            int gi = (r0+row)*32 + so + c8;
            ra_h[i] = gah[gi]; ra_l[i] = gal[gi];
        }
        const unsigned* gbh = (const unsigned*)g_W1h;
        const unsigned* gbl = (const unsigned*)g_W1l;
        #pragma unroll
        for (int i=0;i<6;i++){
            int idx = t + i*256, row = idx>>3, c8 = idx&7;
            int gi = row*64 + s*8 + c8;
            rb_h[i] = gbh[gi]; rb_l[i] = gbl[gi];
        }
    };
    auto store_stage = [&](int buf){
        unsigned* sah = (unsigned*)Ah[buf]; unsigned* sal = (unsigned*)Al[buf];
        #pragma unroll
        for (int i=0;i<2;i++){
            int idx = t + i*256, row = idx>>3, c8 = idx&7;
            sah[row*12+c8] = ra_h[i]; sal[row*12+c8] = ra_l[i];
        }
        unsigned* sbh = (unsigned*)Bh[buf]; unsigned* sbl = (unsigned*)Bl[buf];
        #pragma unroll
        for (int i=0;i<6;i++){
            int idx = t + i*256, row = idx>>3, c8 = idx&7;
            sbh[row*12+c8] = rb_h[i]; sbl[row*12+c8] = rb_l[i];
        }
    };

    load_stage(0); store_stage(0); __syncthreads();
    for (int s=0;s<8;s++){
        int buf = s&1;
        if (s<7) load_stage(s+1);
        const unsigned* As_h = (const unsigned*)Ah[buf];
        const unsigned* As_l = (const unsigned*)Al[buf];
        const unsigned* Bs_h = (const unsigned*)Bh[buf];
        const unsigned* Bs_l = (const unsigned*)Bl[buf];
        unsigned ah[2][4], al[2][4];
        #pragma unroll
        for (int mf=0;mf<2;mf++){
            int mr = wm*32 + mf*16;
            ah[mf][0]=As_h[(mr+g  )*12+tg  ]; ah[mf][1]=As_h[(mr+g+8)*12+tg  ];
            ah[mf][2]=As_h[(mr+g  )*12+tg+4]; ah[mf][3]=As_h[(mr+g+8)*12+tg+4];
            al[mf][0]=As_l[(mr+g  )*12+tg  ]; al[mf][1]=As_l[(mr+g+8)*12+tg  ];
            al[mf][2]=As_l[(mr+g  )*12+tg+4]; al[mf][3]=As_l[(mr+g+8)*12+tg+4];
        }
        #pragma unroll
        for (int nf=0;nf<6;nf++){
            int cb = wn*48 + nf*8 + g;
            unsigned bh0=Bs_h[cb*12+tg], bh1=Bs_h[cb*12+tg+4];
            unsigned bl0=Bs_l[cb*12+tg], bl1=Bs_l[cb*12+tg+4];
            #pragma unroll
            for (int mf=0;mf<2;mf++){
                mma16(Cr[mf][nf], ah[mf], bh0, bh1);
                mma16(Cr[mf][nf], al[mf], bh0, bh1);
                mma16(Cr[mf][nf], ah[mf], bl0, bl1);
            }
        }
        if (s<7){ store_stage((s+1)&1); __syncthreads(); }
    }
    // epilogue: gates
    #pragma unroll
    for (int mf=0;mf<2;mf++)
        #pragma unroll
        for (int nfd=0;nfd<2;nfd++)
            #pragma unroll
            for (int j=0;j<4;j++){
                int row = r0 + wm*32 + mf*16 + g + ((j>>1)<<3);
                int d = wn*16 + nfd*8 + 2*tg + (j&1);
                float ig  = Cr[mf][nfd  ][j] + __ldg(&bias[d]);
                float fgv = Cr[mf][nfd+2][j] + __ldg(&bias[64+d]);
                float hd  = Cr[mf][nfd+4][j] + __ldg(&bias[128+d]);
                g_fg [row*64+d] = sigmf(fgv);
                g_igh[row*64+d] = sigmf(ig)*fmaxf(hd,0.f);
            }
}

// ---- K6: per-chunk affine scan coefficients ----
__global__ void k_seg_ab(){
    int bc = blockIdx.x; int t = threadIdx.x;
    int b = bc>>6, c = bc&63;
    int base = (b*Ss + c*CS)*HD + t;
    float a = 1.f, bb2 = 0.f;
    #pragma unroll 8
    for (int s=0;s<CS;s++){
        float f = g_fg[base + s*HD];
        float gg = g_igh[base + s*HD];
        a *= f; bb2 = bb2*f + gg;
    }
    g_a[bc*HD + t] = a; g_bv[bc*HD + t] = bb2;
}

// ---- K7: chunk-carry scan ----
__global__ void k_carry(const float* __restrict__ initcx){
    int ch = blockIdx.x*blockDim.x + threadIdx.x;
    int b = ch>>9, t = ch&511;
    float cell = initcx[t];
    #pragma unroll
    for (int c=0;c<NC;c++){
        int i = (b*NC + c)*HD + t;
        g_cellin[i] = cell;
        cell = g_a[i]*cell + g_bv[i];
    }
}

// ---- K8: in-chunk cell recurrence (+ bf16 split) ----
__global__ void k_cell(){
    int bc = blockIdx.x; int t = threadIdx.x;
    int b = bc>>6, c = bc&63;
    int base = (b*Ss + c*CS)*HD + t;
    float cell = g_cellin[bc*HD + t];
    #pragma unroll 8
    for (int s=0;s<CS;s++){
        cell = g_fg[base + s*HD]*cell + g_igh[base + s*HD];
        g_cell[base + s*HD] = cell;
        __nv_bfloat16 h,l; split_bf16(cell,h,l);
        g_ch[base+s*HD]=h; g_cl[base+s*HD]=l;
    }
}

// ---- K9: GEMM2 bf16-compensated mma, M64 x N64, fused og*cell ----
__global__ __launch_bounds__(256,2) void k_gemm2(const float* __restrict__ bias,
                                                 float* __restrict__ out){
    __shared__ __nv_bfloat16 Ah[2][64*24], Al[2][64*24];
    __shared__ __nv_bfloat16 Bh[2][64*24], Bl[2][64*24];
    int t = threadIdx.x;
    int r0 = blockIdx.x*64;
    int lane=t&31, wid=t>>5, wm=wid&1, wn=wid>>1;
    int g=lane>>2, tg=lane&3;

    float Cr[2][2][4];
    #pragma unroll
    for (int a=0;a<2;a++)
        #pragma unroll
        for (int b=0;b<2;b++)
            #pragma unroll
            for (int c=0;c<4;c++) Cr[a][b][c]=0.f;

    unsigned ra_h[2], ra_l[2], rb_h[2], rb_l[2];
    auto load_stage = [&](int s){
        const unsigned* gah = (const unsigned*)(s<4 ? g_xh : g_ch);
        const unsigned* gal = (const unsigned*)(s<4 ? g_xl : g_cl);
        int so = (s&3)*8;
        #pragma unroll
        for (int i=0;i<2;i++){
            int idx = t + i*256, row = idx>>3, c8 = idx&7;
            int gi = (r0+row)*32 + so + c8;
            ra_h[i] = gah[gi]; ra_l[i] = gal[gi];
        }
        const unsigned* gbh = (const unsigned*)g_W2h;
        const unsigned* gbl = (const unsigned*)g_W2l;
        #pragma unroll
        for (int i=0;i<2;i++){
            int idx = t + i*256, row = idx>>3, c8 = idx&7;
            int gi = row*64 + s*8 + c8;
            rb_h[i] = gbh[gi]; rb_l[i] = gbl[gi];
        }
    };
    auto store_stage = [&](int buf){
        unsigned* sah=(unsigned*)Ah[buf]; unsigned* sal=(unsigned*)Al[buf];
        unsigned* sbh=(unsigned*)Bh[buf]; unsigned* sbl=(unsigned*)Bl[buf];
        #pragma unroll
        for (int i=0;i<2;i++){
            int idx = t + i*256, row = idx>>3, c8 = idx&7;
            sah[row*12+c8]=ra_h[i]; sal[row*12+c8]=ra_l[i];
            sbh[row*12+c8]=rb_h[i]; sbl[row*12+c8]=rb_l[i];
        }
    };

    load_stage(0); store_stage(0); __syncthreads();
    for (int s=0;s<8;s++){
        int buf = s&1;
        if (s<7) load_stage(s+1);
        const unsigned* As_h=(const unsigned*)Ah[buf];
        const unsigned* As_l=(const unsigned*)Al[buf];
        const unsigned* Bs_h=(const unsigned*)Bh[buf];
        const unsigned* Bs_l=(const unsigned*)Bl[buf];
        unsigned ah[2][4], al[2][4];
        #pragma unroll
        for (int mf=0;mf<2;mf++){
            int mr = wm*32 + mf*16;
            ah[mf][0]=As_h[(mr+g  )*12+tg  ]; ah[mf][1]=As_h[(mr+g+8)*12+tg  ];
            ah[mf][2]=As_h[(mr+g  )*12+tg+4]; ah[mf][3]=As_h[(mr+g+8)*12+tg+4];
            al[mf][0]=As_l[(mr+g  )*12+tg  ]; al[mf][1]=As_l[(mr+g+8)*12+tg  ];
            al[mf][2]=As_l[(mr+g  )*12+tg+4]; al[mf][3]=As_l[(mr+g+8)*12+tg+4];
        }
        #pragma unroll
        for (int nf=0;nf<2;nf++){
            int cb = wn*16 + nf*8 + g;
            unsigned bh0=Bs_h[cb*12+tg], bh1=Bs_h[cb*12+tg+4];
            unsigned bl0=Bs_l[cb*12+tg], bl1=Bs_l[cb*12+tg+4];
            #pragma unroll
            for (int mf=0;mf<2;mf++){
                mma16(Cr[mf][nf], ah[mf], bh0, bh1);
                mma16(Cr[mf][nf], al[mf], bh0, bh1);
                mma16(Cr[mf][nf], ah[mf], bl0, bl1);
            }
        }
        if (s<7){ store_stage((s+1)&1); __syncthreads(); }
    }
    #pragma unroll
    for (int mf=0;mf<2;mf++)
        #pragma unroll
        for (int nf=0;nf<2;nf++)
            #pragma unroll
            for (int j=0;j<4;j++){
                int row = r0 + wm*32 + mf*16 + g + ((j>>1)<<3);
                int col = wn*16 + nf*8 + 2*tg + (j&1);
                float og = sigmf(Cr[mf][nf][j] + __ldg(&bias[col]));
                out[row*64+col] = og * g_cell[row*64+col];
            }
}

extern "C" void kernel_launch(void* const* d_in, const int* in_sizes, int n_in,
                              void* d_out, int out_size){
    const float* x      = (const float*)d_in[0];
    const float* W_hid  = (const float*)d_in[1];
    const float* b_hid  = (const float*)d_in[2];
    const float* W_og   = (const float*)d_in[3];
    const float* b_og   = (const float*)d_in[4];
    const float* gamma  = (const float*)d_in[5];
    const float* beta   = (const float*)d_in[6];
    const float* initcx = (const float*)d_in[7];
    float* out = (float*)d_out;

    k_prepw    <<<256, 128>>>(W_hid, W_og);
    k_chunksum <<<Bb*NC, 512>>>(x);
    k_chunkscan<<<16, 128>>>();
    k_csum     <<<Bb*NC, 512>>>(x);
    k_ln       <<<BSn/16, 512>>>(gamma, beta);
    k_gemm1    <<<Mm/64, 256>>>(b_hid);
    k_seg_ab   <<<Bb*NC, 512>>>();
    k_carry    <<<16, 128>>>(initcx);
    k_cell     <<<Bb*NC, 512>>>();
    k_gemm2    <<<Mm/64, 256>>>(b_og, out);
}